// round 3
// baseline (speedup 1.0000x reference)
#include <cuda_runtime.h>
#include <cuda_bf16.h>
#include <cstdint>
#include <cstddef>

#define DEV __device__ __forceinline__

// ============================================================================
// Device global scratch
// ============================================================================
// A digits, fragment-packed for mma.m16n8k32.s8:
//   [pass(2)][mt(M/16)][kt32(64)][lane(32)] x uint4 (16 int8: a0..a3)
__device__ __align__(256) int8_t g_A[(size_t)2 * 2048 * 64 * 32 * 16];  // 128 MB cap
// B ternary weights (quaternion signs folded), fragment-packed:
//   [nt8(256)][kt32(64)][lane(32)] x uint2 (8 int8: b0,b1)
__device__ __align__(256) int8_t g_B[(size_t)256 * 64 * 32 * 8];        // 4 MB
__device__ float g_rs[32768];      // per-row activation scale s_m
__device__ float g_wmean[4];
__device__ float g_wscale[4];
__device__ float g_outscale;

// ============================================================================
// PTX helpers
// ============================================================================
DEV uint32_t smem_u32(const void* p) {
    uint32_t a;
    asm("{ .reg .u64 t; cvta.to.shared.u64 t, %1; cvt.u32.u64 %0, t; }" : "=r"(a) : "l"(p));
    return a;
}
DEV void cp_async16(uint32_t dst, const void* src) {
    asm volatile("cp.async.cg.shared.global [%0], [%1], 16;" :: "r"(dst), "l"(src) : "memory");
}
DEV void cp_commit() { asm volatile("cp.async.commit_group;" ::: "memory"); }
template <int N> DEV void cp_wait() { asm volatile("cp.async.wait_group %0;" :: "n"(N) : "memory"); }

// mma.sync m16n8k32 s8 x s8 -> s32
DEV void mma_s8(int& d0, int& d1, int& d2, int& d3,
                uint32_t a0, uint32_t a1, uint32_t a2, uint32_t a3,
                uint32_t b0, uint32_t b1) {
    asm volatile(
        "mma.sync.aligned.m16n8k32.row.col.s32.s8.s8.s32 "
        "{%0,%1,%2,%3}, {%4,%5,%6,%7}, {%8,%9}, {%0,%1,%2,%3};"
        : "+r"(d0), "+r"(d1), "+r"(d2), "+r"(d3)
        : "r"(a0), "r"(a1), "r"(a2), "r"(a3), "r"(b0), "r"(b1));
}

DEV unsigned pack4(int a, int b, int c, int d) {
    return (unsigned)(a & 0xFF) | ((unsigned)(b & 0xFF) << 8) |
           ((unsigned)(c & 0xFF) << 16) | ((unsigned)(d & 0xFF) << 24);
}

// ============================================================================
// Kernel 1: per-weight mean / mean|w|
// ============================================================================
__global__ void reduce_w_kernel(const float* __restrict__ rw, const float* __restrict__ iw,
                                const float* __restrict__ jw, const float* __restrict__ kw) {
    const float* ws[4] = {rw, iw, jw, kw};
    const float4* w4 = (const float4*)ws[blockIdx.x];
    float s = 0.f, sa = 0.f;
    for (int idx = threadIdx.x; idx < 65536; idx += 256) {
        float4 v = w4[idx];
        s  += v.x + v.y + v.z + v.w;
        sa += fabsf(v.x) + fabsf(v.y) + fabsf(v.z) + fabsf(v.w);
    }
    __shared__ float sh[64];
    for (int o = 16; o; o >>= 1) {
        s  += __shfl_down_sync(0xFFFFFFFFu, s, o);
        sa += __shfl_down_sync(0xFFFFFFFFu, sa, o);
    }
    int wid = threadIdx.x >> 5, lane = threadIdx.x & 31;
    if (lane == 0) { sh[wid] = s; sh[wid + 32] = sa; }
    __syncthreads();
    if (threadIdx.x == 0) {
        float ts = 0.f, tsa = 0.f;
        for (int q = 0; q < 8; q++) { ts += sh[q]; tsa += sh[q + 32]; }
        g_wmean[blockIdx.x]  = ts / 262144.f;
        g_wscale[blockIdx.x] = fmaxf(tsa / 262144.f, 1e-8f);
    }
}

// ============================================================================
// Quaternion block tables: t = (o>>9)*4 + (k>>9)
// ============================================================================
__device__ __constant__ int   c_sel[16] = {0,1,2,3,  1,0,3,2,  2,3,0,1,  3,2,1,0};
__device__ __constant__ float c_sgn[16] = {1.f,-1.f,-1.f,-1.f,  1.f,1.f,1.f,-1.f,
                                           1.f,-1.f,1.f,1.f,    1.f,1.f,-1.f,1.f};

DEV int quant_w(const float* const* ws, int o, int k) {
    int t = ((o >> 9) << 2) | (k >> 9);
    int s = c_sel[t];
    float w = __ldg(ws[s] + (size_t)(o & 511) * 512 + (k & 511));
    float q = rintf(fminf(fmaxf((w - g_wmean[s]) / g_wscale[s], -1.f), 1.f));
    return (int)(c_sgn[t] * q);
}

// ============================================================================
// Kernel 2: pack W_big into int8 B-fragment layout
//   thread per (nt8, kt32, lane) -> uint2 {b0,b1}
//   b0 = W[n][k0..k0+3], b1 = W[n][k0+16..k0+19]; n = nt*8+lane/4, k0 = kt*32+4*(lane%4)
// ============================================================================
__global__ void pack_w_kernel(const float* __restrict__ rw, const float* __restrict__ iw,
                              const float* __restrict__ jw, const float* __restrict__ kw) {
    int t = blockIdx.x * 256 + threadIdx.x;   // [0, 256*64*32)
    if (t == 0)
        g_outscale = (g_wscale[0] + g_wscale[1] + g_wscale[2] + g_wscale[3]) * 0.125f;
    int lane = t & 31;
    int kt   = (t >> 5) & 63;
    int nt   = t >> 11;
    int n  = nt * 8 + (lane >> 2);
    int k0 = kt * 32 + 4 * (lane & 3);
    const float* ws[4] = {rw, iw, jw, kw};

    uint2 pk;
    pk.x = pack4(quant_w(ws, n, k0),      quant_w(ws, n, k0 + 1),
                 quant_w(ws, n, k0 + 2),  quant_w(ws, n, k0 + 3));
    pk.y = pack4(quant_w(ws, n, k0 + 16), quant_w(ws, n, k0 + 17),
                 quant_w(ws, n, k0 + 18), quant_w(ws, n, k0 + 19));
    ((uint2*)g_B)[t] = pk;
}

// ============================================================================
// Kernel 3: per-row digitize: x[m] = s_m*(d0 + d1/256), fragment-packed digits
//   one block per row m; 256 threads x 8 consecutive floats each
// ============================================================================
__global__ void digitize_kernel(const float* __restrict__ x, int MT) {
    const int m   = blockIdx.x;
    const int tid = threadIdx.x;
    const float4* xr = (const float4*)(x + (size_t)m * 2048);
    float4 v0 = xr[tid * 2];
    float4 v1 = xr[tid * 2 + 1];
    float f[8] = {v0.x, v0.y, v0.z, v0.w, v1.x, v1.y, v1.z, v1.w};

    float mx = 0.f;
#pragma unroll
    for (int q = 0; q < 8; q++) mx = fmaxf(mx, fabsf(f[q]));
    for (int o = 16; o; o >>= 1) mx = fmaxf(mx, __shfl_xor_sync(0xFFFFFFFFu, mx, o));
    __shared__ float sh[8];
    __shared__ float s_inv;
    if ((tid & 31) == 0) sh[tid >> 5] = mx;
    __syncthreads();
    if (tid == 0) {
        float mv = sh[0];
#pragma unroll
        for (int q = 1; q < 8; q++) mv = fmaxf(mv, sh[q]);
        mv = fmaxf(mv, 1e-20f);
        g_rs[m] = mv / 127.f;
        s_inv   = 127.f / mv;
    }
    __syncthreads();
    const float inv = s_inv;

    const int mt = m >> 4, r0 = m & 15;
    uint32_t* A32 = (uint32_t*)g_A;
    const size_t pass_stride = (size_t)MT * 64 * 32 * 4;   // uint32 units
#pragma unroll
    for (int gi = 0; gi < 2; gi++) {
        int i0[4], i1[4];
#pragma unroll
        for (int e = 0; e < 4; e++) {
            float t0 = f[gi * 4 + e] * inv;        // in [-127, 127]
            int d0 = __float2int_rn(t0);
            int d1 = __float2int_rn((t0 - (float)d0) * 256.f);
            if (d1 > 127) d1 = 127;
            i0[e] = d0; i1[e] = d1;
        }
        int g    = tid * 2 + gi;        // k-group of 4 (k0 = 4g)
        int kt32 = g >> 3;
        int gq   = g & 7;
        int c    = gq & 3;
        int kh   = gq >> 2;
        int lane = (r0 & 7) * 4 + c;
        int slot = (r0 >> 3) + (kh << 1);
        size_t idx = ((((size_t)mt * 64) + kt32) * 32 + lane) * 4 + slot;
        A32[idx]               = pack4(i0[0], i0[1], i0[2], i0[3]);
        A32[idx + pass_stride] = pack4(i1[0], i1[1], i1[2], i1[3]);
    }
}

// ============================================================================
// Kernel 4: int8 GEMM  out = (s_m*(P0 + P1/256) + bias) * osc
//   CTA tile 128x128, K-tile 64 (2 x k32), 8 warps (4m x 2n, warp 32x64)
//   6-stage cp.async pipeline; 64 iterations = 2 digit passes x 32 ktiles.
// ============================================================================
static constexpr int NS = 6;
static constexpr int STAGE_BYTES = 16384;             // A 8KB + B 8KB
static constexpr int GEMM_SMEM   = NS * STAGE_BYTES;  // 96 KB

__global__ void __launch_bounds__(256, 1)
quat_gemm_kernel(float* __restrict__ out, const float* __restrict__ bias, int MT) {
    extern __shared__ char smem[];
    const uint32_t smem_base = smem_u32(smem);
    const int tid    = threadIdx.x;
    const int lane   = tid & 31;
    const int wid    = tid >> 5;
    const int warp_m = wid & 3;
    const int warp_n = wid >> 2;
    const int mtile0 = blockIdx.y * 8;      // 8 m16-tiles per CTA
    const int nt0    = blockIdx.x * 16;     // 16 n8-tiles per CTA

    const int NIT = 64;                     // 2 passes x 32 k64-tiles

    int   iacc[2][8][4];
    float facc[2][8][4];
#pragma unroll
    for (int i = 0; i < 2; i++)
#pragma unroll
        for (int j = 0; j < 8; j++)
#pragma unroll
            for (int q = 0; q < 4; q++) iacc[i][j][q] = 0;

    auto issue_stage = [&](int s, int i) {
        const int pass = i >> 5;
        const int kt   = i & 31;            // k64-tile -> kt32 pair {2kt, 2kt+1}
        const char* Ab = (const char*)g_A +
            (((size_t)pass * MT + mtile0) * 64 + kt * 2) * 512;
        const char* Bb = (const char*)g_B + ((size_t)nt0 * 64 + kt * 2) * 256;
        const uint32_t sA = smem_base + s * STAGE_BYTES;
        const uint32_t sB = sA + 8192;
#pragma unroll
        for (int u = 0; u < 2; u++) {
            int t = tid + u * 256;          // [0,512)
            int mtl = t >> 6, remA = t & 63;
            cp_async16(sA + t * 16, Ab + (size_t)mtl * 32768 + remA * 16);
            int ntl = t >> 5, remB = t & 31;
            cp_async16(sB + t * 16, Bb + (size_t)ntl * 16384 + remB * 16);
        }
        cp_commit();
    };

    issue_stage(0, 0);
    issue_stage(1, 1);
    issue_stage(2, 2);
    issue_stage(3, 3);
    issue_stage(4, 4);

#pragma unroll 1
    for (int i = 0; i < NIT; ++i) {
        if (i + 5 < NIT) issue_stage((i + 5) % NS, i + 5);
        else             cp_commit();
        cp_wait<NS - 1>();
        __syncthreads();

        const int s = i % NS;
        const uint4* Asm = (const uint4*)(smem + s * STAGE_BYTES);
        const uint2* Bsm = (const uint2*)(smem + s * STAGE_BYTES + 8192);
#pragma unroll
        for (int ks = 0; ks < 2; ks++) {
            uint4 a[2];
            uint2 b[8];
#pragma unroll
            for (int mtl = 0; mtl < 2; mtl++)
                a[mtl] = Asm[((warp_m * 2 + mtl) * 2 + ks) * 32 + lane];
#pragma unroll
            for (int ntl = 0; ntl < 8; ntl++)
                b[ntl] = Bsm[((warp_n * 8 + ntl) * 2 + ks) * 32 + lane];
#pragma unroll
            for (int mtl = 0; mtl < 2; mtl++)
#pragma unroll
                for (int ntl = 0; ntl < 8; ntl++)
                    mma_s8(iacc[mtl][ntl][0], iacc[mtl][ntl][1],
                           iacc[mtl][ntl][2], iacc[mtl][ntl][3],
                           a[mtl].x, a[mtl].y, a[mtl].z, a[mtl].w,
                           b[ntl].x, b[ntl].y);
        }
        __syncthreads();

        if (i == 31) {      // pass 0 (hi digit) done: stash as float, reset
#pragma unroll
            for (int mtl = 0; mtl < 2; mtl++)
#pragma unroll
                for (int ntl = 0; ntl < 8; ntl++)
#pragma unroll
                    for (int q = 0; q < 4; q++) {
                        facc[mtl][ntl][q] = (float)iacc[mtl][ntl][q];
                        iacc[mtl][ntl][q] = 0;
                    }
        }
    }

    // ---- epilogue: out = (s_m*(P0 + P1/256) + bias) * osc ----
    const float osc = g_outscale;
    const int r = lane >> 2, c = lane & 3;
    const int m_base = (mtile0 + warp_m * 2) * 16 + r;
    const int n_base = nt0 * 8 + warp_n * 64 + 2 * c;
#pragma unroll
    for (int mtl = 0; mtl < 2; mtl++) {
        const int mrow = m_base + mtl * 16;
        const float sa = g_rs[mrow];
        const float sb = g_rs[mrow + 8];
#pragma unroll
        for (int ntl = 0; ntl < 8; ntl++) {
            const int nc = n_base + ntl * 8;
            float2 bv = *(const float2*)(bias + nc);
            float p0 = facc[mtl][ntl][0] + (float)iacc[mtl][ntl][0] * 0.00390625f;
            float p1 = facc[mtl][ntl][1] + (float)iacc[mtl][ntl][1] * 0.00390625f;
            float p2 = facc[mtl][ntl][2] + (float)iacc[mtl][ntl][2] * 0.00390625f;
            float p3 = facc[mtl][ntl][3] + (float)iacc[mtl][ntl][3] * 0.00390625f;
            float2 o0, o1;
            o0.x = (p0 * sa + bv.x) * osc;
            o0.y = (p1 * sa + bv.y) * osc;
            o1.x = (p2 * sb + bv.x) * osc;
            o1.y = (p3 * sb + bv.y) * osc;
            *(float2*)(out + (size_t)mrow * 2048 + nc)       = o0;
            *(float2*)(out + (size_t)(mrow + 8) * 2048 + nc) = o1;
        }
    }
}

// ============================================================================
// Host launch — graph-capturable: kernel launches only
// ============================================================================
extern "C" void kernel_launch(void* const* d_in, const int* in_sizes, int n_in,
                              void* d_out, int out_size) {
    const float* x    = (const float*)d_in[0];
    const float* rw   = (const float*)d_in[1];
    const float* iw   = (const float*)d_in[2];
    const float* jw   = (const float*)d_in[3];
    const float* kw   = (const float*)d_in[4];
    const float* bias = (const float*)d_in[5];
    float* out = (float*)d_out;
    const int M  = in_sizes[0] / 2048;   // 16384
    const int MT = M / 16;

    reduce_w_kernel<<<4, 256>>>(rw, iw, jw, kw);
    pack_w_kernel<<<(256 * 64 * 32) / 256, 256>>>(rw, iw, jw, kw);
    digitize_kernel<<<M, 256>>>(x, MT);

    static int attr_done = 0;
    if (!attr_done) {
        cudaFuncSetAttribute(quat_gemm_kernel,
                             cudaFuncAttributeMaxDynamicSharedMemorySize, GEMM_SMEM);
        attr_done = 1;
    }
    dim3 grid(2048 / 128, M / 128);      // x = n fastest (A-tile reuse in L2)
    quat_gemm_kernel<<<grid, 256, GEMM_SMEM>>>(out, bias, MT);
}

// round 4
// speedup vs baseline: 4.8483x; 4.8483x over previous
#include <cuda_runtime.h>
#include <cuda_fp16.h>
#include <cstdint>
#include <cstddef>

#define DEV __device__ __forceinline__

// ============================================================================
// Device global scratch
// ============================================================================
// A fp16 activations, fragment-packed for mma.m16n8k16:
//   [mt(M/16)][kt16(128)][lane(32)] x uint4 (regs a0..a3)
__device__ __align__(256) __half g_A[(size_t)32768 * 2048];   // 64 MB cap (M<=32768? M=16384 -> 64MB)
// B ternary fp16 weights (quaternion signs folded), PAIR-packed:
//   [ntp(128)][kt16(128)][lane(32)] x uint4 {b0_even,b1_even,b0_odd,b1_odd}
__device__ __align__(256) __half g_B[(size_t)2048 * 2048];    // 8 MB
__device__ float g_wmean[4];
__device__ float g_wscale[4];
__device__ float g_outscale;

// ============================================================================
// PTX helpers
// ============================================================================
DEV uint32_t smem_u32(const void* p) {
    uint32_t a;
    asm("{ .reg .u64 t; cvta.to.shared.u64 t, %1; cvt.u32.u64 %0, t; }" : "=r"(a) : "l"(p));
    return a;
}
DEV void cp_async16(uint32_t dst, const void* src) {
    asm volatile("cp.async.cg.shared.global [%0], [%1], 16;" :: "r"(dst), "l"(src) : "memory");
}
DEV void cp_commit() { asm volatile("cp.async.commit_group;" ::: "memory"); }
template <int N> DEV void cp_wait() { asm volatile("cp.async.wait_group %0;" :: "n"(N) : "memory"); }

// mma.sync m16n8k16, fp16 x fp16 -> f32
DEV void mma_f16(float& d0, float& d1, float& d2, float& d3,
                 uint32_t a0, uint32_t a1, uint32_t a2, uint32_t a3,
                 uint32_t b0, uint32_t b1) {
    asm volatile(
        "mma.sync.aligned.m16n8k16.row.col.f32.f16.f16.f32 "
        "{%0,%1,%2,%3}, {%4,%5,%6,%7}, {%8,%9}, {%0,%1,%2,%3};"
        : "+f"(d0), "+f"(d1), "+f"(d2), "+f"(d3)
        : "r"(a0), "r"(a1), "r"(a2), "r"(a3), "r"(b0), "r"(b1));
}

// ============================================================================
// Kernel 1: per-weight mean / mean|w|
// ============================================================================
__global__ void reduce_w_kernel(const float* __restrict__ rw, const float* __restrict__ iw,
                                const float* __restrict__ jw, const float* __restrict__ kw) {
    const float* ws[4] = {rw, iw, jw, kw};
    const float4* w4 = (const float4*)ws[blockIdx.x];
    float s = 0.f, sa = 0.f;
    for (int idx = threadIdx.x; idx < 65536; idx += 256) {
        float4 v = w4[idx];
        s  += v.x + v.y + v.z + v.w;
        sa += fabsf(v.x) + fabsf(v.y) + fabsf(v.z) + fabsf(v.w);
    }
    __shared__ float sh[64];
    for (int o = 16; o; o >>= 1) {
        s  += __shfl_down_sync(0xFFFFFFFFu, s, o);
        sa += __shfl_down_sync(0xFFFFFFFFu, sa, o);
    }
    int wid = threadIdx.x >> 5, lane = threadIdx.x & 31;
    if (lane == 0) { sh[wid] = s; sh[wid + 32] = sa; }
    __syncthreads();
    if (threadIdx.x == 0) {
        float ts = 0.f, tsa = 0.f;
        for (int q = 0; q < 8; q++) { ts += sh[q]; tsa += sh[q + 32]; }
        g_wmean[blockIdx.x]  = ts / 262144.f;
        g_wscale[blockIdx.x] = fmaxf(tsa / 262144.f, 1e-8f);
    }
}

// ============================================================================
// Quaternion block tables: t = (o>>9)*4 + (k>>9)
// ============================================================================
__device__ __constant__ int   c_sel[16] = {0,1,2,3,  1,0,3,2,  2,3,0,1,  3,2,1,0};
__device__ __constant__ float c_sgn[16] = {1.f,-1.f,-1.f,-1.f,  1.f,1.f,1.f,-1.f,
                                           1.f,-1.f,1.f,1.f,    1.f,1.f,-1.f,1.f};

DEV float quant_w(const float* const* ws, int o, int k) {
    int t = ((o >> 9) << 2) | (k >> 9);
    int s = c_sel[t];
    float w = __ldg(ws[s] + (size_t)(o & 511) * 512 + (k & 511));
    float q = rintf(fminf(fmaxf((w - g_wmean[s]) / g_wscale[s], -1.f), 1.f));
    return c_sgn[t] * q;
}

DEV unsigned h2u(float a, float b) {
    __half2 h = __floats2half2_rn(a, b);
    return *reinterpret_cast<unsigned*>(&h);
}

// ============================================================================
// Kernel 2: pack W_big into PAIRED fp16 B-fragment layout
//   thread per (ntp, kt16, lane) -> uint4:
//     .x = {W[o0][k0],W[o0][k0+1]}   .y = {W[o0][k0+8],W[o0][k0+9]}
//     .z = {W[o1][k0],W[o1][k0+1]}   .w = {W[o1][k0+8],W[o1][k0+9]}
//   o0 = ntp*16 + lane/4, o1 = o0 + 8, k0 = kt*16 + 2*(lane%4)
// ============================================================================
__global__ void pack_w_kernel(const float* __restrict__ rw, const float* __restrict__ iw,
                              const float* __restrict__ jw, const float* __restrict__ kw) {
    int t = blockIdx.x * 256 + threadIdx.x;          // [0, 128*128*32)
    if (t == 0)
        g_outscale = (g_wscale[0] + g_wscale[1] + g_wscale[2] + g_wscale[3]) * 0.125f;
    int lane = t & 31;
    int kt   = (t >> 5) & 127;
    int ntp  = t >> 12;
    int o0 = ntp * 16 + (lane >> 2);
    int o1 = o0 + 8;
    int k0 = kt * 16 + 2 * (lane & 3);
    const float* ws[4] = {rw, iw, jw, kw};

    uint4 pk;
    pk.x = h2u(quant_w(ws, o0, k0),     quant_w(ws, o0, k0 + 1));
    pk.y = h2u(quant_w(ws, o0, k0 + 8), quant_w(ws, o0, k0 + 9));
    pk.z = h2u(quant_w(ws, o1, k0),     quant_w(ws, o1, k0 + 1));
    pk.w = h2u(quant_w(ws, o1, k0 + 8), quant_w(ws, o1, k0 + 9));
    ((uint4*)g_B)[t] = pk;
}

// ============================================================================
// Kernel 3: convert x (f32) to fp16, packed into mma A-fragment layout
//   thread per (mt, kt16, lane) -> uint4 {a0..a3}
// ============================================================================
__global__ void pack_x_kernel(const float* __restrict__ x, int MT) {
    int t = blockIdx.x * 256 + threadIdx.x;          // [0, MT*128*32)
    int lane = t & 31;
    int kt   = (t >> 5) & 127;
    int mt   = t >> 12;
    int r  = lane >> 2, c = lane & 3;
    int row0 = mt * 16 + r;
    int k0   = kt * 16 + 2 * c;

    float2 v00 = *(const float2*)(x + (size_t)row0 * 2048 + k0);
    float2 v10 = *(const float2*)(x + (size_t)(row0 + 8) * 2048 + k0);
    float2 v01 = *(const float2*)(x + (size_t)row0 * 2048 + k0 + 8);
    float2 v11 = *(const float2*)(x + (size_t)(row0 + 8) * 2048 + k0 + 8);

    uint4 pk;
    pk.x = h2u(v00.x, v00.y);
    pk.y = h2u(v10.x, v10.y);
    pk.z = h2u(v01.x, v01.y);
    pk.w = h2u(v11.x, v11.y);
    ((uint4*)g_A)[t] = pk;
}

// ============================================================================
// Kernel 4: fp16 GEMM  out[M,2048] = (A @ W_big^T + bias) * osc
//   CTA tile 128x128, K-tile 32 (2 x k16), 8 warps (4m x 2n, warp 32x64)
//   4-stage cp.async pipeline; 64 iterations (single pass, K=2048).
// ============================================================================
static constexpr int NS = 4;
static constexpr int STAGE_BYTES = 16384;             // A 8KB + B 8KB
static constexpr int GEMM_SMEM   = NS * STAGE_BYTES;  // 64 KB

__global__ void __launch_bounds__(256, 2)
quat_gemm_kernel(float* __restrict__ out, const float* __restrict__ bias, int MT) {
    extern __shared__ char smem[];
    const uint32_t smem_base = smem_u32(smem);
    const int tid    = threadIdx.x;
    const int lane   = tid & 31;
    const int wid    = tid >> 5;
    const int warp_m = wid & 3;           // 0..3
    const int warp_n = wid >> 2;          // 0..1
    const int mtile0 = blockIdx.y * 8;    // 8 m16-tiles per CTA
    const int ntp0   = blockIdx.x * 8;    // 8 n16-pairs per CTA (=16 n8-tiles)

    const uint4* A4 = (const uint4*)g_A;
    const uint4* B4 = (const uint4*)g_B;
    const int NIT = 64;                   // K=2048 / 32

    float acc[2][8][4];
#pragma unroll
    for (int i = 0; i < 2; i++)
#pragma unroll
        for (int j = 0; j < 8; j++)
#pragma unroll
            for (int q = 0; q < 4; q++) acc[i][j][q] = 0.f;

    auto issue_stage = [&](int s, int i) {
        const int kt32 = i;                     // k16 tiles {2i, 2i+1}
        const uint4* Ab = A4 + (((size_t)mtile0) * 128 + kt32 * 2) * 32;
        const uint4* Bb = B4 + (((size_t)ntp0) * 128 + kt32 * 2) * 32;
        const uint32_t sA = smem_base + s * STAGE_BYTES;
        const uint32_t sB = sA + 8192;
#pragma unroll
        for (int u = 0; u < 2; u++) {
            int t = tid + u * 256;              // [0,512)
            int mtl = t >> 6, rem = t & 63;     // rem covers 2 k16 x 32 lanes
            cp_async16(sA + t * 16, Ab + (size_t)mtl * 4096 + rem);
            cp_async16(sB + t * 16, Bb + (size_t)mtl * 4096 + rem);  // ntp stride == mt stride
        }
        cp_commit();
    };

    issue_stage(0, 0);
    issue_stage(1, 1);
    issue_stage(2, 2);

#pragma unroll 1
    for (int i = 0; i < NIT; ++i) {
        if (i + 3 < NIT) issue_stage((i + 3) & 3, i + 3);
        else             cp_commit();           // keep group count uniform
        cp_wait<3>();
        __syncthreads();

        const int s = i & 3;
        const uint4* Asm = (const uint4*)(smem + s * STAGE_BYTES);
        const uint4* Bsm = (const uint4*)(smem + s * STAGE_BYTES + 8192);
#pragma unroll
        for (int ks = 0; ks < 2; ks++) {
            uint4 a[2];
            uint4 bq[4];
#pragma unroll
            for (int mtl = 0; mtl < 2; mtl++)
                a[mtl] = Asm[((warp_m * 2 + mtl) * 2 + ks) * 32 + lane];
#pragma unroll
            for (int p = 0; p < 4; p++)
                bq[p] = Bsm[((warp_n * 4 + p) * 2 + ks) * 32 + lane];
#pragma unroll
            for (int mtl = 0; mtl < 2; mtl++)
#pragma unroll
                for (int p = 0; p < 4; p++) {
                    mma_f16(acc[mtl][2 * p][0], acc[mtl][2 * p][1],
                            acc[mtl][2 * p][2], acc[mtl][2 * p][3],
                            a[mtl].x, a[mtl].y, a[mtl].z, a[mtl].w,
                            bq[p].x, bq[p].y);
                    mma_f16(acc[mtl][2 * p + 1][0], acc[mtl][2 * p + 1][1],
                            acc[mtl][2 * p + 1][2], acc[mtl][2 * p + 1][3],
                            a[mtl].x, a[mtl].y, a[mtl].z, a[mtl].w,
                            bq[p].z, bq[p].w);
                }
        }
        __syncthreads();
    }

    // ---- epilogue: (acc + bias) * osc, direct float2 stores ----
    const float osc = g_outscale;
    const int r = lane >> 2, c = lane & 3;
    const int m_base = (mtile0 + warp_m * 2) * 16 + r;
    const int n_base = ntp0 * 16 + warp_n * 64 + 2 * c;
#pragma unroll
    for (int mtl = 0; mtl < 2; mtl++) {
        const int mrow = m_base + mtl * 16;
#pragma unroll
        for (int ntl = 0; ntl < 8; ntl++) {
            const int nc = n_base + ntl * 8;
            float2 bv = *(const float2*)(bias + nc);
            float2 o0, o1;
            o0.x = (acc[mtl][ntl][0] + bv.x) * osc;
            o0.y = (acc[mtl][ntl][1] + bv.y) * osc;
            o1.x = (acc[mtl][ntl][2] + bv.x) * osc;
            o1.y = (acc[mtl][ntl][3] + bv.y) * osc;
            *(float2*)(out + (size_t)mrow * 2048 + nc)       = o0;
            *(float2*)(out + (size_t)(mrow + 8) * 2048 + nc) = o1;
        }
    }
}

// ============================================================================
// Host launch — graph-capturable: kernel launches only
// ============================================================================
extern "C" void kernel_launch(void* const* d_in, const int* in_sizes, int n_in,
                              void* d_out, int out_size) {
    const float* x    = (const float*)d_in[0];
    const float* rw   = (const float*)d_in[1];
    const float* iw   = (const float*)d_in[2];
    const float* jw   = (const float*)d_in[3];
    const float* kw   = (const float*)d_in[4];
    const float* bias = (const float*)d_in[5];
    float* out = (float*)d_out;
    const int M  = in_sizes[0] / 2048;   // 16384
    const int MT = M / 16;

    reduce_w_kernel<<<4, 256>>>(rw, iw, jw, kw);
    pack_w_kernel<<<(128 * 128 * 32) / 256, 256>>>(rw, iw, jw, kw);
    pack_x_kernel<<<(MT * 128 * 32) / 256, 256>>>(x, MT);

    cudaFuncSetAttribute(quat_gemm_kernel,
                         cudaFuncAttributeMaxDynamicSharedMemorySize, GEMM_SMEM);
    dim3 grid(2048 / 128, M / 128);      // x = n fastest (A-tile reuse in L2)
    quat_gemm_kernel<<<grid, 256, GEMM_SMEM>>>(out, bias, MT);
}

// round 5
// speedup vs baseline: 5.4024x; 1.1143x over previous
#include <cuda_runtime.h>
#include <cuda_fp16.h>
#include <cstdint>
#include <cstddef>

#define DEV __device__ __forceinline__

// ============================================================================
// Device global scratch
// ============================================================================
// A fp16 activations, fragment-packed for mma.m16n8k16:
//   [mt(M/16)][kt16(128)][lane(32)] x uint4 (regs a0..a3)
__device__ __align__(256) __half g_A[(size_t)32768 * 2048];   // cap
// B ternary fp16 weights (quaternion signs folded), PAIR-packed:
//   [ntp(128)][kt16(128)][lane(32)] x uint4 {b0_even,b1_even,b0_odd,b1_odd}
__device__ __align__(256) __half g_B[(size_t)2048 * 2048];
__device__ float g_wmean[4];
__device__ float g_wscale[4];
__device__ float g_outscale;

// ============================================================================
// PTX helpers
// ============================================================================
DEV uint32_t smem_u32(const void* p) {
    uint32_t a;
    asm("{ .reg .u64 t; cvta.to.shared.u64 t, %1; cvt.u32.u64 %0, t; }" : "=r"(a) : "l"(p));
    return a;
}
DEV void cp_async16(uint32_t dst, const void* src) {
    asm volatile("cp.async.cg.shared.global [%0], [%1], 16;" :: "r"(dst), "l"(src) : "memory");
}
DEV void cp_commit() { asm volatile("cp.async.commit_group;" ::: "memory"); }
template <int N> DEV void cp_wait() { asm volatile("cp.async.wait_group %0;" :: "n"(N) : "memory"); }

// mma.sync m16n8k16, fp16 x fp16 -> f32
DEV void mma_f16(float& d0, float& d1, float& d2, float& d3,
                 uint32_t a0, uint32_t a1, uint32_t a2, uint32_t a3,
                 uint32_t b0, uint32_t b1) {
    asm volatile(
        "mma.sync.aligned.m16n8k16.row.col.f32.f16.f16.f32 "
        "{%0,%1,%2,%3}, {%4,%5,%6,%7}, {%8,%9}, {%0,%1,%2,%3};"
        : "+f"(d0), "+f"(d1), "+f"(d2), "+f"(d3)
        : "r"(a0), "r"(a1), "r"(a2), "r"(a3), "r"(b0), "r"(b1));
}

// ============================================================================
// Kernel 1: per-weight mean / mean|w|
// ============================================================================
__global__ void reduce_w_kernel(const float* __restrict__ rw, const float* __restrict__ iw,
                                const float* __restrict__ jw, const float* __restrict__ kw) {
    const float* ws[4] = {rw, iw, jw, kw};
    const float4* w4 = (const float4*)ws[blockIdx.x];
    float s = 0.f, sa = 0.f;
    for (int idx = threadIdx.x; idx < 65536; idx += 256) {
        float4 v = w4[idx];
        s  += v.x + v.y + v.z + v.w;
        sa += fabsf(v.x) + fabsf(v.y) + fabsf(v.z) + fabsf(v.w);
    }
    __shared__ float sh[64];
    for (int o = 16; o; o >>= 1) {
        s  += __shfl_down_sync(0xFFFFFFFFu, s, o);
        sa += __shfl_down_sync(0xFFFFFFFFu, sa, o);
    }
    int wid = threadIdx.x >> 5, lane = threadIdx.x & 31;
    if (lane == 0) { sh[wid] = s; sh[wid + 32] = sa; }
    __syncthreads();
    if (threadIdx.x == 0) {
        float ts = 0.f, tsa = 0.f;
        for (int q = 0; q < 8; q++) { ts += sh[q]; tsa += sh[q + 32]; }
        g_wmean[blockIdx.x]  = ts / 262144.f;
        g_wscale[blockIdx.x] = fmaxf(tsa / 262144.f, 1e-8f);
    }
}

// ============================================================================
// Quaternion block tables: t = (o>>9)*4 + (k>>9)
// ============================================================================
__device__ __constant__ int   c_sel[16] = {0,1,2,3,  1,0,3,2,  2,3,0,1,  3,2,1,0};
__device__ __constant__ float c_sgn[16] = {1.f,-1.f,-1.f,-1.f,  1.f,1.f,1.f,-1.f,
                                           1.f,-1.f,1.f,1.f,    1.f,1.f,-1.f,1.f};

DEV float quant_w(const float* const* ws, int o, int k) {
    int t = ((o >> 9) << 2) | (k >> 9);
    int s = c_sel[t];
    float w = __ldg(ws[s] + (size_t)(o & 511) * 512 + (k & 511));
    float q = rintf(fminf(fmaxf((w - g_wmean[s]) / g_wscale[s], -1.f), 1.f));
    return c_sgn[t] * q;
}

DEV unsigned h2u(float a, float b) {
    __half2 h = __floats2half2_rn(a, b);
    return *reinterpret_cast<unsigned*>(&h);
}

// ============================================================================
// Kernel 2: pack W_big into PAIRED fp16 B-fragment layout
// ============================================================================
__global__ void pack_w_kernel(const float* __restrict__ rw, const float* __restrict__ iw,
                              const float* __restrict__ jw, const float* __restrict__ kw) {
    int t = blockIdx.x * 256 + threadIdx.x;          // [0, 128*128*32)
    if (t == 0)
        g_outscale = (g_wscale[0] + g_wscale[1] + g_wscale[2] + g_wscale[3]) * 0.125f;
    int lane = t & 31;
    int kt   = (t >> 5) & 127;
    int ntp  = t >> 12;
    int o0 = ntp * 16 + (lane >> 2);
    int o1 = o0 + 8;
    int k0 = kt * 16 + 2 * (lane & 3);
    const float* ws[4] = {rw, iw, jw, kw};

    uint4 pk;
    pk.x = h2u(quant_w(ws, o0, k0),     quant_w(ws, o0, k0 + 1));
    pk.y = h2u(quant_w(ws, o0, k0 + 8), quant_w(ws, o0, k0 + 9));
    pk.z = h2u(quant_w(ws, o1, k0),     quant_w(ws, o1, k0 + 1));
    pk.w = h2u(quant_w(ws, o1, k0 + 8), quant_w(ws, o1, k0 + 9));
    ((uint4*)g_B)[t] = pk;
}

// ============================================================================
// Kernel 3: smem-staged x -> fp16 fragment pack (coalesced both sides)
//   block = one mt (16 rows x 2048 cols). smem row stride 2056 halves
//   (1028 words ≡ 4 mod 32 -> conflict-free fragment gather).
// ============================================================================
static constexpr int PACKX_SMEM = 16 * 2056 * 2;   // 65792 B

__global__ void pack_x_kernel(const float* __restrict__ x) {
    extern __shared__ __half sx[];                 // [16][2056]
    const int mt  = blockIdx.x;
    const int tid = threadIdx.x;
    const float4* xr = (const float4*)(x + (size_t)mt * 16 * 2048);
#pragma unroll
    for (int u = 0; u < 32; u++) {
        int idx = tid + u * 256;                   // [0, 8192)
        int r  = idx >> 9;
        int c4 = idx & 511;
        float4 v = xr[idx];
        __half2 h0 = __floats2half2_rn(v.x, v.y);
        __half2 h1 = __floats2half2_rn(v.z, v.w);
        *(__half2*)(sx + r * 2056 + c4 * 4)     = h0;
        *(__half2*)(sx + r * 2056 + c4 * 4 + 2) = h1;
    }
    __syncthreads();
    uint4* A4 = (uint4*)g_A;
#pragma unroll
    for (int u = 0; u < 16; u++) {
        int idx  = tid + u * 256;                  // [0, 4096) = kt*32 + lane
        int lane = idx & 31;
        int kt   = idx >> 5;
        int r  = lane >> 2, c = lane & 3;
        int k0 = kt * 16 + 2 * c;
        uint4 pk;
        pk.x = *(const uint32_t*)(sx + r * 2056 + k0);
        pk.y = *(const uint32_t*)(sx + (r + 8) * 2056 + k0);
        pk.z = *(const uint32_t*)(sx + r * 2056 + k0 + 8);
        pk.w = *(const uint32_t*)(sx + (r + 8) * 2056 + k0 + 8);
        A4[(size_t)mt * 4096 + idx] = pk;
    }
}

// ============================================================================
// Kernel 4: fp16 GEMM  out[M,2048] = (A @ W_big^T + bias) * osc
//   CTA tile 128x128, 4 warps (2m x 2n), warp tile 64x64.
//   K-tile 32 (2 x k16), 4-stage cp.async pipeline, 64 iterations.
// ============================================================================
static constexpr int NS = 4;
static constexpr int STAGE_BYTES = 16384;             // A 8KB + B 8KB
static constexpr int GEMM_SMEM   = NS * STAGE_BYTES;  // 64 KB

__global__ void __launch_bounds__(128, 2)
quat_gemm_kernel(float* __restrict__ out, const float* __restrict__ bias, int MT) {
    extern __shared__ char smem[];
    const uint32_t smem_base = smem_u32(smem);
    const int tid    = threadIdx.x;
    const int lane   = tid & 31;
    const int wid    = tid >> 5;
    const int warp_m = wid & 1;           // 0..1
    const int warp_n = wid >> 1;          // 0..1
    const int mtile0 = blockIdx.y * 8;    // 8 m16-tiles per CTA
    const int ntp0   = blockIdx.x * 8;    // 8 n16-pairs per CTA

    const uint4* A4 = (const uint4*)g_A;
    const uint4* B4 = (const uint4*)g_B;
    const int NIT = 64;                   // K=2048 / 32

    float acc[4][8][4];
#pragma unroll
    for (int i = 0; i < 4; i++)
#pragma unroll
        for (int j = 0; j < 8; j++)
#pragma unroll
            for (int q = 0; q < 4; q++) acc[i][j][q] = 0.f;

    auto issue_stage = [&](int s, int i) {
        const uint4* Ab = A4 + (((size_t)mtile0) * 128 + i * 2) * 32;
        const uint4* Bb = B4 + (((size_t)ntp0) * 128 + i * 2) * 32;
        const uint32_t sA = smem_base + s * STAGE_BYTES;
        const uint32_t sB = sA + 8192;
#pragma unroll
        for (int u = 0; u < 4; u++) {
            int t = tid + u * 128;              // [0,512)
            int mtl = t >> 6, rem = t & 63;     // rem covers 2 k16 x 32 lanes
            cp_async16(sA + t * 16, Ab + (size_t)mtl * 4096 + rem);
            cp_async16(sB + t * 16, Bb + (size_t)mtl * 4096 + rem);
        }
        cp_commit();
    };

    issue_stage(0, 0);
    issue_stage(1, 1);
    issue_stage(2, 2);

#pragma unroll 1
    for (int i = 0; i < NIT; ++i) {
        if (i + 3 < NIT) issue_stage((i + 3) & 3, i + 3);
        else             cp_commit();           // keep group count uniform
        cp_wait<3>();
        __syncthreads();

        const int s = i & 3;
        const uint4* Asm = (const uint4*)(smem + s * STAGE_BYTES);
        const uint4* Bsm = (const uint4*)(smem + s * STAGE_BYTES + 8192);
#pragma unroll
        for (int ks = 0; ks < 2; ks++) {
            uint4 a[4];
            uint4 bq[4];
#pragma unroll
            for (int mtl = 0; mtl < 4; mtl++)
                a[mtl] = Asm[((warp_m * 4 + mtl) * 2 + ks) * 32 + lane];
#pragma unroll
            for (int p = 0; p < 4; p++)
                bq[p] = Bsm[((warp_n * 4 + p) * 2 + ks) * 32 + lane];
#pragma unroll
            for (int mtl = 0; mtl < 4; mtl++)
#pragma unroll
                for (int p = 0; p < 4; p++) {
                    mma_f16(acc[mtl][2 * p][0], acc[mtl][2 * p][1],
                            acc[mtl][2 * p][2], acc[mtl][2 * p][3],
                            a[mtl].x, a[mtl].y, a[mtl].z, a[mtl].w,
                            bq[p].x, bq[p].y);
                    mma_f16(acc[mtl][2 * p + 1][0], acc[mtl][2 * p + 1][1],
                            acc[mtl][2 * p + 1][2], acc[mtl][2 * p + 1][3],
                            a[mtl].x, a[mtl].y, a[mtl].z, a[mtl].w,
                            bq[p].z, bq[p].w);
                }
        }
        __syncthreads();
    }

    // ---- epilogue: (acc + bias) * osc, direct float2 stores ----
    const float osc = g_outscale;
    const int r = lane >> 2, c = lane & 3;
    const int m_base = (mtile0 + warp_m * 4) * 16 + r;
    const int n_base = ntp0 * 16 + warp_n * 64 + 2 * c;
#pragma unroll
    for (int mtl = 0; mtl < 4; mtl++) {
        const int mrow = m_base + mtl * 16;
#pragma unroll
        for (int ntl = 0; ntl < 8; ntl++) {
            const int nc = n_base + ntl * 8;
            float2 bv = *(const float2*)(bias + nc);
            float2 o0, o1;
            o0.x = (acc[mtl][ntl][0] + bv.x) * osc;
            o0.y = (acc[mtl][ntl][1] + bv.y) * osc;
            o1.x = (acc[mtl][ntl][2] + bv.x) * osc;
            o1.y = (acc[mtl][ntl][3] + bv.y) * osc;
            *(float2*)(out + (size_t)mrow * 2048 + nc)       = o0;
            *(float2*)(out + (size_t)(mrow + 8) * 2048 + nc) = o1;
        }
    }
}

// ============================================================================
// Host launch — graph-capturable: kernel launches only
// ============================================================================
extern "C" void kernel_launch(void* const* d_in, const int* in_sizes, int n_in,
                              void* d_out, int out_size) {
    const float* x    = (const float*)d_in[0];
    const float* rw   = (const float*)d_in[1];
    const float* iw   = (const float*)d_in[2];
    const float* jw   = (const float*)d_in[3];
    const float* kw   = (const float*)d_in[4];
    const float* bias = (const float*)d_in[5];
    float* out = (float*)d_out;
    const int M  = in_sizes[0] / 2048;   // 16384
    const int MT = M / 16;

    reduce_w_kernel<<<4, 256>>>(rw, iw, jw, kw);
    pack_w_kernel<<<(128 * 128 * 32) / 256, 256>>>(rw, iw, jw, kw);

    cudaFuncSetAttribute(pack_x_kernel,
                         cudaFuncAttributeMaxDynamicSharedMemorySize, PACKX_SMEM);
    pack_x_kernel<<<MT, 256, PACKX_SMEM>>>(x);

    cudaFuncSetAttribute(quat_gemm_kernel,
                         cudaFuncAttributeMaxDynamicSharedMemorySize, GEMM_SMEM);
    dim3 grid(2048 / 128, M / 128);      // x = n fastest (A-tile reuse in L2)
    quat_gemm_kernel<<<grid, 128, GEMM_SMEM>>>(out, bias, MT);
}

// round 6
// speedup vs baseline: 6.0668x; 1.1230x over previous
#include <cuda_runtime.h>
#include <cuda_fp16.h>
#include <cstdint>
#include <cstddef>

#define DEV __device__ __forceinline__

// ============================================================================
// Device global scratch
// ============================================================================
// A fp16 activations, fragment-packed for mma.m16n8k16:
//   [mt(M/16)][kt16(128)][lane(32)] x uint4 (regs a0..a3)
__device__ __align__(256) __half g_A[(size_t)32768 * 2048];
// B ternary fp16 weights (quaternion signs folded), PAIR-packed:
//   [ntp(128)][kt16(128)][lane(32)] x uint4 {b0_even,b1_even,b0_odd,b1_odd}
__device__ __align__(256) __half g_B[(size_t)2048 * 2048];
__device__ float g_part[128][2];     // partial sums: [slice*4+w][{sum, abs}]
__device__ float g_wmean[4];
__device__ float g_wscale[4];
__device__ float g_outscale;

// ============================================================================
// PTX helpers
// ============================================================================
DEV uint32_t smem_u32(const void* p) {
    uint32_t a;
    asm("{ .reg .u64 t; cvta.to.shared.u64 t, %1; cvt.u32.u64 %0, t; }" : "=r"(a) : "l"(p));
    return a;
}
DEV void cp_async16(uint32_t dst, const void* src) {
    asm volatile("cp.async.cg.shared.global [%0], [%1], 16;" :: "r"(dst), "l"(src) : "memory");
}
DEV void cp_commit() { asm volatile("cp.async.commit_group;" ::: "memory"); }
template <int N> DEV void cp_wait() { asm volatile("cp.async.wait_group %0;" :: "n"(N) : "memory"); }

// mma.sync m16n8k16, fp16 x fp16 -> f32
DEV void mma_f16(float& d0, float& d1, float& d2, float& d3,
                 uint32_t a0, uint32_t a1, uint32_t a2, uint32_t a3,
                 uint32_t b0, uint32_t b1) {
    asm volatile(
        "mma.sync.aligned.m16n8k16.row.col.f32.f16.f16.f32 "
        "{%0,%1,%2,%3}, {%4,%5,%6,%7}, {%8,%9}, {%0,%1,%2,%3};"
        : "+f"(d0), "+f"(d1), "+f"(d2), "+f"(d3)
        : "r"(a0), "r"(a1), "r"(a2), "r"(a3), "r"(b0), "r"(b1));
}

// ============================================================================
// Kernel 1a: partial per-weight mean / mean|w| (128 blocks = 4 weights x 32 slices)
// ============================================================================
__global__ void reduce_w_kernel(const float* __restrict__ rw, const float* __restrict__ iw,
                                const float* __restrict__ jw, const float* __restrict__ kw) {
    const float* ws[4] = {rw, iw, jw, kw};
    const int w     = blockIdx.x & 3;
    const int slice = blockIdx.x >> 2;
    const float4* w4 = (const float4*)ws[w] + (size_t)slice * 2048;
    float s = 0.f, sa = 0.f;
#pragma unroll
    for (int u = 0; u < 8; u++) {
        float4 v = w4[threadIdx.x + u * 256];
        s  += v.x + v.y + v.z + v.w;
        sa += fabsf(v.x) + fabsf(v.y) + fabsf(v.z) + fabsf(v.w);
    }
    __shared__ float sh[16];
    for (int o = 16; o; o >>= 1) {
        s  += __shfl_down_sync(0xFFFFFFFFu, s, o);
        sa += __shfl_down_sync(0xFFFFFFFFu, sa, o);
    }
    int wid = threadIdx.x >> 5, lane = threadIdx.x & 31;
    if (lane == 0) { sh[wid] = s; sh[wid + 8] = sa; }
    __syncthreads();
    if (threadIdx.x == 0) {
        float ts = 0.f, tsa = 0.f;
#pragma unroll
        for (int q = 0; q < 8; q++) { ts += sh[q]; tsa += sh[q + 8]; }
        g_part[blockIdx.x][0] = ts;
        g_part[blockIdx.x][1] = tsa;
    }
}

// ============================================================================
// Kernel 1b: deterministic finalize (1 block)
// ============================================================================
__global__ void finalize_w_kernel() {
    int w = threadIdx.x;
    if (w < 4) {
        float ts = 0.f, tsa = 0.f;
#pragma unroll
        for (int q = 0; q < 32; q++) {
            ts  += g_part[q * 4 + w][0];
            tsa += g_part[q * 4 + w][1];
        }
        g_wmean[w]  = ts / 262144.f;
        g_wscale[w] = fmaxf(tsa / 262144.f, 1e-8f);
    }
    __syncthreads();
    if (w == 0)
        g_outscale = (g_wscale[0] + g_wscale[1] + g_wscale[2] + g_wscale[3]) * 0.125f;
}

// ============================================================================
// Quaternion block tables: t = (o>>9)*4 + (k>>9)
// ============================================================================
__device__ __constant__ int   c_sel[16] = {0,1,2,3,  1,0,3,2,  2,3,0,1,  3,2,1,0};
__device__ __constant__ float c_sgn[16] = {1.f,-1.f,-1.f,-1.f,  1.f,1.f,1.f,-1.f,
                                           1.f,-1.f,1.f,1.f,    1.f,1.f,-1.f,1.f};

DEV float quant_w(const float* const* ws, int o, int k) {
    int t = ((o >> 9) << 2) | (k >> 9);
    int s = c_sel[t];
    float w = __ldg(ws[s] + (size_t)(o & 511) * 512 + (k & 511));
    float q = rintf(fminf(fmaxf((w - g_wmean[s]) / g_wscale[s], -1.f), 1.f));
    return c_sgn[t] * q;
}

DEV unsigned h2u(float a, float b) {
    __half2 h = __floats2half2_rn(a, b);
    return *reinterpret_cast<unsigned*>(&h);
}

// ============================================================================
// Kernel 2: pack W_big into PAIRED fp16 B-fragment layout
// ============================================================================
__global__ void pack_w_kernel(const float* __restrict__ rw, const float* __restrict__ iw,
                              const float* __restrict__ jw, const float* __restrict__ kw) {
    int t = blockIdx.x * 256 + threadIdx.x;          // [0, 128*128*32)
    int lane = t & 31;
    int kt   = (t >> 5) & 127;
    int ntp  = t >> 12;
    int o0 = ntp * 16 + (lane >> 2);
    int o1 = o0 + 8;
    int k0 = kt * 16 + 2 * (lane & 3);
    const float* ws[4] = {rw, iw, jw, kw};

    uint4 pk;
    pk.x = h2u(quant_w(ws, o0, k0),     quant_w(ws, o0, k0 + 1));
    pk.y = h2u(quant_w(ws, o0, k0 + 8), quant_w(ws, o0, k0 + 9));
    pk.z = h2u(quant_w(ws, o1, k0),     quant_w(ws, o1, k0 + 1));
    pk.w = h2u(quant_w(ws, o1, k0 + 8), quant_w(ws, o1, k0 + 9));
    ((uint4*)g_B)[t] = pk;
}

// ============================================================================
// Kernel 3: smem-staged x -> fp16 fragment pack (coalesced both sides)
// ============================================================================
static constexpr int PACKX_SMEM = 16 * 2056 * 2;   // 65792 B

__global__ void pack_x_kernel(const float* __restrict__ x) {
    extern __shared__ __half sx[];                 // [16][2056]
    const int mt  = blockIdx.x;
    const int tid = threadIdx.x;
    const float4* xr = (const float4*)(x + (size_t)mt * 16 * 2048);
#pragma unroll
    for (int u = 0; u < 32; u++) {
        int idx = tid + u * 256;                   // [0, 8192)
        int r  = idx >> 9;
        int c4 = idx & 511;
        float4 v = xr[idx];
        __half2 h0 = __floats2half2_rn(v.x, v.y);
        __half2 h1 = __floats2half2_rn(v.z, v.w);
        *(__half2*)(sx + r * 2056 + c4 * 4)     = h0;
        *(__half2*)(sx + r * 2056 + c4 * 4 + 2) = h1;
    }
    __syncthreads();
    uint4* A4 = (uint4*)g_A;
#pragma unroll
    for (int u = 0; u < 16; u++) {
        int idx  = tid + u * 256;                  // [0, 4096) = kt*32 + lane
        int lane = idx & 31;
        int kt   = idx >> 5;
        int r  = lane >> 2, c = lane & 3;
        int k0 = kt * 16 + 2 * c;
        uint4 pk;
        pk.x = *(const uint32_t*)(sx + r * 2056 + k0);
        pk.y = *(const uint32_t*)(sx + (r + 8) * 2056 + k0);
        pk.z = *(const uint32_t*)(sx + r * 2056 + k0 + 8);
        pk.w = *(const uint32_t*)(sx + (r + 8) * 2056 + k0 + 8);
        A4[(size_t)mt * 4096 + idx] = pk;
    }
}

// ============================================================================
// Kernel 4: fp16 GEMM  out[M,2048] = (A @ W_big^T + bias) * osc
//   CTA tile 128x128, 4 warps (2m x 2n), warp tile 64x64.
//   K-tile 32 (2 x k16), 4-stage cp.async pipeline, ONE sync per iteration.
// ============================================================================
static constexpr int NS = 4;
static constexpr int STAGE_BYTES = 16384;             // A 8KB + B 8KB
static constexpr int GEMM_SMEM   = NS * STAGE_BYTES;  // 64 KB

__global__ void __launch_bounds__(128, 2)
quat_gemm_kernel(float* __restrict__ out, const float* __restrict__ bias, int MT) {
    extern __shared__ char smem[];
    const uint32_t smem_base = smem_u32(smem);
    const int tid    = threadIdx.x;
    const int lane   = tid & 31;
    const int wid    = tid >> 5;
    const int warp_m = wid & 1;           // 0..1
    const int warp_n = wid >> 1;          // 0..1
    const int mtile0 = blockIdx.y * 8;    // 8 m16-tiles per CTA
    const int ntp0   = blockIdx.x * 8;    // 8 n16-pairs per CTA

    const uint4* A4 = (const uint4*)g_A;
    const uint4* B4 = (const uint4*)g_B;
    const int NIT = 64;                   // K=2048 / 32

    float acc[4][8][4];
#pragma unroll
    for (int i = 0; i < 4; i++)
#pragma unroll
        for (int j = 0; j < 8; j++)
#pragma unroll
            for (int q = 0; q < 4; q++) acc[i][j][q] = 0.f;

    auto issue_stage = [&](int s, int i) {
        const uint4* Ab = A4 + (((size_t)mtile0) * 128 + i * 2) * 32;
        const uint4* Bb = B4 + (((size_t)ntp0) * 128 + i * 2) * 32;
        const uint32_t sA = smem_base + s * STAGE_BYTES;
        const uint32_t sB = sA + 8192;
#pragma unroll
        for (int u = 0; u < 4; u++) {
            int t = tid + u * 128;              // [0,512)
            int mtl = t >> 6, rem = t & 63;     // rem covers 2 k16 x 32 lanes
            cp_async16(sA + t * 16, Ab + (size_t)mtl * 4096 + rem);
            cp_async16(sB + t * 16, Bb + (size_t)mtl * 4096 + rem);
        }
        cp_commit();
    };

    issue_stage(0, 0);
    issue_stage(1, 1);
    issue_stage(2, 2);

#pragma unroll 1
    for (int i = 0; i < NIT; ++i) {
        cp_wait<2>();                           // stage i has landed
        __syncthreads();                        // all warps done reading stage i-1
        if (i + 3 < NIT) issue_stage((i + 3) & 3, i + 3);
        else             cp_commit();           // keep group count uniform

        const int s = i & 3;
        const uint4* Asm = (const uint4*)(smem + s * STAGE_BYTES);
        const uint4* Bsm = (const uint4*)(smem + s * STAGE_BYTES + 8192);
#pragma unroll
        for (int ks = 0; ks < 2; ks++) {
            uint4 a[4];
            uint4 bq[4];
#pragma unroll
            for (int mtl = 0; mtl < 4; mtl++)
                a[mtl] = Asm[((warp_m * 4 + mtl) * 2 + ks) * 32 + lane];
#pragma unroll
            for (int p = 0; p < 4; p++)
                bq[p] = Bsm[((warp_n * 4 + p) * 2 + ks) * 32 + lane];
#pragma unroll
            for (int mtl = 0; mtl < 4; mtl++)
#pragma unroll
                for (int p = 0; p < 4; p++) {
                    mma_f16(acc[mtl][2 * p][0], acc[mtl][2 * p][1],
                            acc[mtl][2 * p][2], acc[mtl][2 * p][3],
                            a[mtl].x, a[mtl].y, a[mtl].z, a[mtl].w,
                            bq[p].x, bq[p].y);
                    mma_f16(acc[mtl][2 * p + 1][0], acc[mtl][2 * p + 1][1],
                            acc[mtl][2 * p + 1][2], acc[mtl][2 * p + 1][3],
                            a[mtl].x, a[mtl].y, a[mtl].z, a[mtl].w,
                            bq[p].z, bq[p].w);
                }
        }
    }

    // ---- epilogue: (acc + bias) * osc, direct float2 stores ----
    const float osc = g_outscale;
    const int r = lane >> 2, c = lane & 3;
    const int m_base = (mtile0 + warp_m * 4) * 16 + r;
    const int n_base = ntp0 * 16 + warp_n * 64 + 2 * c;
#pragma unroll
    for (int mtl = 0; mtl < 4; mtl++) {
        const int mrow = m_base + mtl * 16;
#pragma unroll
        for (int ntl = 0; ntl < 8; ntl++) {
            const int nc = n_base + ntl * 8;
            float2 bv = *(const float2*)(bias + nc);
            float2 o0, o1;
            o0.x = (acc[mtl][ntl][0] + bv.x) * osc;
            o0.y = (acc[mtl][ntl][1] + bv.y) * osc;
            o1.x = (acc[mtl][ntl][2] + bv.x) * osc;
            o1.y = (acc[mtl][ntl][3] + bv.y) * osc;
            *(float2*)(out + (size_t)mrow * 2048 + nc)       = o0;
            *(float2*)(out + (size_t)(mrow + 8) * 2048 + nc) = o1;
        }
    }
}

// ============================================================================
// Host launch — graph-capturable: kernel launches only
// ============================================================================
extern "C" void kernel_launch(void* const* d_in, const int* in_sizes, int n_in,
                              void* d_out, int out_size) {
    const float* x    = (const float*)d_in[0];
    const float* rw   = (const float*)d_in[1];
    const float* iw   = (const float*)d_in[2];
    const float* jw   = (const float*)d_in[3];
    const float* kw   = (const float*)d_in[4];
    const float* bias = (const float*)d_in[5];
    float* out = (float*)d_out;
    const int M  = in_sizes[0] / 2048;   // 16384
    const int MT = M / 16;

    reduce_w_kernel<<<128, 256>>>(rw, iw, jw, kw);
    finalize_w_kernel<<<1, 32>>>();
    pack_w_kernel<<<(128 * 128 * 32) / 256, 256>>>(rw, iw, jw, kw);

    cudaFuncSetAttribute(pack_x_kernel,
                         cudaFuncAttributeMaxDynamicSharedMemorySize, PACKX_SMEM);
    pack_x_kernel<<<MT, 256, PACKX_SMEM>>>(x);

    cudaFuncSetAttribute(quat_gemm_kernel,
                         cudaFuncAttributeMaxDynamicSharedMemorySize, GEMM_SMEM);
    dim3 grid(2048 / 128, M / 128);      // x = n fastest (A-tile reuse in L2)
    quat_gemm_kernel<<<grid, 128, GEMM_SMEM>>>(out, bias, MT);
}